// round 16
// baseline (speedup 1.0000x reference)
#include <cuda_runtime.h>
#include <cuda_bf16.h>
#include <math.h>
#include <stdint.h>

#define BATCH 2
#define SEQ   2048
#define EMB   1024
#define NH    16
#define HD    64

// Scratch: pre-split bf16 planes. Q/K in [B,H,S,D], V TRANSPOSED in [B,H,D,S].
// Q planes are pre-scaled by log2(e)/8. g_att fp32 [B,H,S,D] for the O proj.
__device__ __nv_bfloat16 g_Qhi[BATCH*NH*SEQ*HD];
__device__ __nv_bfloat16 g_Qlo[BATCH*NH*SEQ*HD];
__device__ __nv_bfloat16 g_Khi[BATCH*NH*SEQ*HD];
__device__ __nv_bfloat16 g_Klo[BATCH*NH*SEQ*HD];
__device__ __nv_bfloat16 g_Vhi[BATCH*NH*SEQ*HD];
__device__ __nv_bfloat16 g_Vlo[BATCH*NH*SEQ*HD];
__device__ float         g_att[BATCH*NH*SEQ*HD];

#define LOG2E 1.4426950408889634f

// ===========================================================================
// helpers
// ===========================================================================
__device__ __forceinline__ uint32_t smem_u32(const void* p) {
    uint32_t a;
    asm("{ .reg .u64 t; cvta.to.shared.u64 t, %1; cvt.u32.u64 %0, t; }"
        : "=r"(a) : "l"(p));
    return a;
}
__device__ __forceinline__ void sts_v2(uint32_t a, uint32_t x, uint32_t y) {
    asm volatile("st.shared.v2.b32 [%0], {%1, %2};" :: "r"(a), "r"(x), "r"(y) : "memory");
}
__device__ __forceinline__ void cp16(uint32_t dst, const void* src) {
    asm volatile("cp.async.cg.shared.global [%0], [%1], 16;"
                 :: "r"(dst), "l"(src) : "memory");
}
__device__ __forceinline__ float ex2(float x) {
    float r;
    asm("ex2.approx.f32 %0, %1;" : "=f"(r) : "f"(x));
    return r;
}
// ldmatrix x4: 4 8x8 bf16 matrices in one instruction
__device__ __forceinline__ void ldsm4(uint32_t* r, uint32_t addr) {
    asm volatile("ldmatrix.sync.aligned.m8n8.x4.shared.b16 {%0,%1,%2,%3}, [%4];"
                 : "=r"(r[0]), "=r"(r[1]), "=r"(r[2]), "=r"(r[3]) : "r"(addr));
}

// bf16 MMA m16n8k16, fp32 accumulate (portable path, sm_80+)
__device__ __forceinline__ void mma16816(float* c, const uint32_t* a, const uint32_t* b) {
    asm volatile(
        "mma.sync.aligned.m16n8k16.row.col.f32.bf16.bf16.f32 "
        "{%0,%1,%2,%3}, {%4,%5,%6,%7}, {%8,%9}, {%0,%1,%2,%3};"
        : "+f"(c[0]), "+f"(c[1]), "+f"(c[2]), "+f"(c[3])
        : "r"(a[0]), "r"(a[1]), "r"(a[2]), "r"(a[3]), "r"(b[0]), "r"(b[1]));
}

__device__ __forceinline__ uint32_t pkbf(__nv_bfloat16 a, __nv_bfloat16 b) {
    return ((uint32_t)__bfloat16_as_ushort(b) << 16) | __bfloat16_as_ushort(a);
}
__device__ __forceinline__ void split2(float x, float y, uint32_t& hi, uint32_t& lo) {
    __nv_bfloat16 hx = __float2bfloat16(x);
    __nv_bfloat16 hy = __float2bfloat16(y);
    hi = pkbf(hx, hy);
    lo = pkbf(__float2bfloat16(x - __bfloat162float(hx)),
              __float2bfloat16(y - __bfloat162float(hy)));
}
__device__ __forceinline__ uint4 split4(float4 v) {
    uint4 u;
    split2(v.x, v.y, u.x, u.z);
    split2(v.z, v.w, u.y, u.w);
    return u;
}

// ===========================================================================
// Projection GEMM core: 4096x1024 @ 1024x1024^T + bias, bf16 3-plane split.
// CTA 128x128, 512 threads / 16 warps (4Mx4N), warp tile 32x32, BK=32,
// double-buffered smem pitch 80B, fragments via ldmatrix.x4.
// 16 warps/SM (vs 8 at 256thr) -> 2x latency-hiding pool.
// ===========================================================================
#define BK      32
#define PITCHB  80
#define PLANE   (128*PITCHB)
#define BUFSZ   (4*PLANE)
#define PJ_SMEM (2*BUFSZ)           // 81920 B
#define PJ_THR  512

// A-frag ldmatrix lane mapping
__device__ __forceinline__ uint32_t asel(int lane) {
    return (uint32_t)(((lane & 7) + ((lane >> 3) & 1) * 8) * PITCHB + (lane >> 4) * 16);
}
// B-pair mapping
__device__ __forceinline__ uint32_t bsel(int lane, int pitch) {
    return (uint32_t)((((lane >> 4) << 3) | (lane & 7)) * pitch + ((lane & 8) ? 16 : 0));
}

// Shared GEMM body. MODEA: 0 = A linear, 1 = A from [B,H,S,D].
template<int MODEA>
__device__ __forceinline__ void proj_body(
    const float* __restrict__ A, const float* __restrict__ W,
    uint32_t sb, int m0, int n0, float acc[2][4][4])
{
    const int tid  = threadIdx.x;
    const int wid  = tid >> 5, lane = tid & 31;
    const int wM   = wid >> 2;          // 0..3
    const int wN   = wid & 3;           // 0..3
    const uint32_t tA = asel(lane);
    const uint32_t tB = bsel(lane, PITCHB);

    float4 avA[2], avW[2];

    auto gload = [&](int kb) {
        const int k0 = kb * BK;
        #pragma unroll
        for (int i = 0; i < 2; i++) {
            const int idx = i * PJ_THR + tid;
            const int r = idx >> 3, c4 = (idx & 7) << 2;
            if (MODEA == 1) {
                const int m = m0 + r;
                const int b = m >> 11, s = m & 2047;
                const int k = k0 + c4;
                const int h = k >> 6, d = k & 63;
                avA[i] = *(const float4*)(A + ((size_t)((b*NH + h)*SEQ + s))*HD + d);
            } else {
                avA[i] = *(const float4*)(A + (size_t)(m0 + r) * EMB + k0 + c4);
            }
            avW[i] = *(const float4*)(W + (size_t)(n0 + r) * EMB + k0 + c4);
        }
    };

    auto cvtstore = [&](int buf) {
        const uint32_t base = sb + (uint32_t)buf * BUFSZ;
        #pragma unroll
        for (int i = 0; i < 2; i++) {
            const int idx = i * PJ_THR + tid;
            const int r = idx >> 3, c4 = (idx & 7) << 2;
            const uint32_t off = (uint32_t)(r * PITCHB + c4 * 2);
            uint4 ua = split4(avA[i]);
            sts_v2(base + off,              ua.x, ua.y);
            sts_v2(base + PLANE + off,      ua.z, ua.w);
            uint4 uw = split4(avW[i]);
            sts_v2(base + 2*PLANE + off,    uw.x, uw.y);
            sts_v2(base + 3*PLANE + off,    uw.z, uw.w);
        }
    };

    auto mma_chunk = [&](int buf) {
        const uint32_t aH = sb + (uint32_t)buf * BUFSZ;
        #pragma unroll
        for (int ks = 0; ks < 2; ks++) {
            const uint32_t kOff = (uint32_t)(ks * 32);
            uint32_t Ah[2][4], Al[2][4], Bh[2][4], Bl[2][4];
            #pragma unroll
            for (int mt = 0; mt < 2; mt++) {
                const uint32_t ro = (uint32_t)((wM*32 + mt*16) * PITCHB) + kOff + tA;
                ldsm4(Ah[mt], aH + ro);
                ldsm4(Al[mt], aH + PLANE + ro);
            }
            #pragma unroll
            for (int p = 0; p < 2; p++) {
                const uint32_t ro = (uint32_t)((wN*32 + p*16) * PITCHB) + kOff + tB;
                ldsm4(Bh[p], aH + 2*PLANE + ro);
                ldsm4(Bl[p], aH + 3*PLANE + ro);
            }
            #pragma unroll
            for (int mt = 0; mt < 2; mt++)
                #pragma unroll
                for (int p = 0; p < 2; p++) {
                    mma16816(acc[mt][2*p],   Ah[mt], Bh[p]);
                    mma16816(acc[mt][2*p],   Al[mt], Bh[p]);
                    mma16816(acc[mt][2*p],   Ah[mt], Bl[p]);
                    mma16816(acc[mt][2*p+1], Ah[mt], Bh[p] + 2);
                    mma16816(acc[mt][2*p+1], Al[mt], Bh[p] + 2);
                    mma16816(acc[mt][2*p+1], Ah[mt], Bl[p] + 2);
                }
        }
    };

    gload(0);
    cvtstore(0);
    __syncthreads();

    for (int kb = 0; kb < EMB/BK; kb++) {
        const int cur = kb & 1;
        if (kb < EMB/BK - 1) gload(kb + 1);
        mma_chunk(cur);
        if (kb < EMB/BK - 1) {
            cvtstore(cur ^ 1);
            __syncthreads();
        }
    }
}

// Merged Q/K/V projection: blockIdx.z selects {query,key,value}.
// z<2 -> bf16 planes [B,H,S,D]; z==2 -> planes transposed [B,H,D,S].
__global__ void __launch_bounds__(PJ_THR, 1)
qkv_mma(const float* __restrict__ q, const float* __restrict__ k,
        const float* __restrict__ v,
        const float* __restrict__ Wq, const float* __restrict__ Wk,
        const float* __restrict__ Wv,
        const float* __restrict__ bq, const float* __restrict__ bk,
        const float* __restrict__ bv,
        __nv_bfloat16* __restrict__ qh, __nv_bfloat16* __restrict__ ql,
        __nv_bfloat16* __restrict__ kh, __nv_bfloat16* __restrict__ kl,
        __nv_bfloat16* __restrict__ vh, __nv_bfloat16* __restrict__ vl)
{
    extern __shared__ char smp[];
    const uint32_t sb = smem_u32(smp);
    const int z = blockIdx.z;
    const float* A    = (z == 0) ? q  : (z == 1) ? k  : v;
    const float* W    = (z == 0) ? Wq : (z == 1) ? Wk : Wv;
    const float* bias = (z == 0) ? bq : (z == 1) ? bk : bv;
    __nv_bfloat16* Chi = (z == 0) ? qh : (z == 1) ? kh : vh;
    __nv_bfloat16* Clo = (z == 0) ? ql : (z == 1) ? kl : vl;
    const float scale = (z == 0) ? 0.125f * LOG2E : 1.0f;

    const int n0 = blockIdx.x * 128;
    const int m0 = blockIdx.y * 128;

    float acc[2][4][4];
    #pragma unroll
    for (int mt = 0; mt < 2; mt++)
        #pragma unroll
        for (int nt = 0; nt < 4; nt++)
            #pragma unroll
            for (int i = 0; i < 4; i++) acc[mt][nt][i] = 0.f;

    proj_body<0>(A, W, sb, m0, n0, acc);

    const int tid = threadIdx.x;
    const int wid = tid >> 5, lane = tid & 31;
    const int g = lane >> 2, tg = lane & 3;
    const int wM = wid >> 2, wN = wid & 3;

    #pragma unroll
    for (int mt = 0; mt < 2; mt++) {
        #pragma unroll
        for (int nt = 0; nt < 4; nt++) {
            const int row0 = m0 + wM*32 + mt*16 + g;
            const int col  = n0 + wN*32 + nt*8 + tg*2;
            float2 bv2 = *(const float2*)(bias + col);
            float2 v0, v1;
            v0.x = (acc[mt][nt][0] + bv2.x) * scale;
            v0.y = (acc[mt][nt][1] + bv2.y) * scale;
            v1.x = (acc[mt][nt][2] + bv2.x) * scale;
            v1.y = (acc[mt][nt][3] + bv2.y) * scale;
            const int h = col >> 6, d = col & 63;
            if (z < 2) {
                uint32_t hi, lo;
                {
                    const int b = row0 >> 11, s = row0 & 2047;
                    const size_t idx = ((size_t)((b*NH + h)*SEQ + s))*HD + d;
                    split2(v0.x, v0.y, hi, lo);
                    *(uint32_t*)(Chi + idx) = hi;
                    *(uint32_t*)(Clo + idx) = lo;
                }
                {
                    const int r1 = row0 + 8;
                    const int b = r1 >> 11, s = r1 & 2047;
                    const size_t idx = ((size_t)((b*NH + h)*SEQ + s))*HD + d;
                    split2(v1.x, v1.y, hi, lo);
                    *(uint32_t*)(Chi + idx) = hi;
                    *(uint32_t*)(Clo + idx) = lo;
                }
            } else {
                const int b = row0 >> 11, s = row0 & 2047;
                __nv_bfloat16* bhp = Chi + ((size_t)(b*NH + h))*HD*SEQ;
                __nv_bfloat16* blp = Clo + ((size_t)(b*NH + h))*HD*SEQ;
                #pragma unroll
                for (int qq = 0; qq < 4; qq++) {
                    const float vv = (qq==0) ? v0.x : (qq==1) ? v0.y : (qq==2) ? v1.x : v1.y;
                    const int dd = d + (qq & 1);
                    const int ss = s + ((qq >> 1) << 3);
                    __nv_bfloat16 hb = __float2bfloat16(vv);
                    __nv_bfloat16 lb = __float2bfloat16(vv - __bfloat162float(hb));
                    bhp[(size_t)dd*SEQ + ss] = hb;
                    blp[(size_t)dd*SEQ + ss] = lb;
                }
            }
        }
    }
}

// Output projection: A from fp32 [B,H,S,D] (g_att), C fp32 linear.
__global__ void __launch_bounds__(PJ_THR, 1)
oproj_mma(const float* __restrict__ A, const float* __restrict__ W,
          const float* __restrict__ bias, float* __restrict__ Cf)
{
    extern __shared__ char smp[];
    const uint32_t sb = smem_u32(smp);
    const int n0 = blockIdx.x * 128;
    const int m0 = blockIdx.y * 128;

    float acc[2][4][4];
    #pragma unroll
    for (int mt = 0; mt < 2; mt++)
        #pragma unroll
        for (int nt = 0; nt < 4; nt++)
            #pragma unroll
            for (int i = 0; i < 4; i++) acc[mt][nt][i] = 0.f;

    proj_body<1>(A, W, sb, m0, n0, acc);

    const int tid = threadIdx.x;
    const int wid = tid >> 5, lane = tid & 31;
    const int g = lane >> 2, tg = lane & 3;
    const int wM = wid >> 2, wN = wid & 3;

    #pragma unroll
    for (int mt = 0; mt < 2; mt++) {
        #pragma unroll
        for (int nt = 0; nt < 4; nt++) {
            const int row0 = m0 + wM*32 + mt*16 + g;
            const int col  = n0 + wN*32 + nt*8 + tg*2;
            float2 bv = *(const float2*)(bias + col);
            float2 v0, v1;
            v0.x = acc[mt][nt][0] + bv.x;  v0.y = acc[mt][nt][1] + bv.y;
            v1.x = acc[mt][nt][2] + bv.x;  v1.y = acc[mt][nt][3] + bv.y;
            *(float2*)(Cf + (size_t)row0 * EMB + col) = v0;
            *(float2*)(Cf + (size_t)(row0 + 8) * EMB + col) = v1;
        }
    }
}

// ===========================================================================
// Flash attention via warp-level bf16 MMA. CTA: 8 warps x 16 q-rows = 128.
// K/V tiles staged by cp.async from PRE-SPLIT bf16 planes, double-buffered.
// Fragment loads via ldmatrix.x4. Softmax base-2 (Q pre-scaled by log2e/8).
// Forced 2 CTAs/SM (128 regs).
// ===========================================================================
#define AT_PITCH 144
#define AT_PL    (64*AT_PITCH)          // 9216 per plane
#define AT_BUF   (4*AT_PL)              // KHI,KLO,VHI,VLO = 36864
#define AT_RK    (2*AT_BUF)             // 73728
#define AT_SMEM  (AT_RK + SEQ*4)        // 81920

__global__ void __launch_bounds__(256, 2)
attn_mma(const int* __restrict__ responses, const int* __restrict__ mask,
         const float* __restrict__ Wm, const float* __restrict__ bm)
{
    extern __shared__ char sma[];
    const uint32_t sb = smem_u32(sma);
    float* rkf = (float*)(sma + AT_RK);

    const int tid  = threadIdx.x;
    const int wid  = tid >> 5, lane = tid & 31;
    const int g    = lane >> 2, tg = lane & 3;
    const int qb = blockIdx.x, h = blockIdx.y, b = blockIdx.z;
    const int q0 = qb * 128;
    const int rowA = q0 + wid * 16 + g;
    const int rowB = rowA + 8;
    const uint32_t tB = bsel(lane, AT_PITCH);

    const float Wmh = Wm[h], bmh = bm[h];
    const float A0c = (Wmh + bmh) * LOG2E;
    const float A1c = Wmh * 0.0625f * LOG2E;
    const float rqA = (float)responses[b*SEQ + rowA];
    const float rqB = (float)responses[b*SEQ + rowB];

    const size_t hb64 = (size_t)(b*NH + h) * SEQ * HD;
    const __nv_bfloat16* Qhg = g_Qhi + hb64;
    const __nv_bfloat16* Qlg = g_Qlo + hb64;
    const __nv_bfloat16* Khg = g_Khi + hb64;
    const __nv_bfloat16* Klg = g_Klo + hb64;
    const __nv_bfloat16* Vhg = g_Vhi + hb64;   // [d][s]
    const __nv_bfloat16* Vlg = g_Vlo + hb64;
    const int*   Mb  = mask + (size_t)b*SEQ*SEQ;
    const int*   rkp = responses + b*SEQ;

    for (int i = tid; i < SEQ; i += 256) rkf[i] = (float)rkp[i];

    // ---- preload Q A-frags from pre-split (pre-scaled) planes ----
    uint32_t Qhi[4][4], Qlo[4][4];
    #pragma unroll
    for (int kc = 0; kc < 4; kc++) {
        const int c0 = kc*16 + tg*2;
        Qhi[kc][0] = *(const uint32_t*)(Qhg + (size_t)rowA*HD + c0);
        Qhi[kc][1] = *(const uint32_t*)(Qhg + (size_t)rowB*HD + c0);
        Qhi[kc][2] = *(const uint32_t*)(Qhg + (size_t)rowA*HD + c0 + 8);
        Qhi[kc][3] = *(const uint32_t*)(Qhg + (size_t)rowB*HD + c0 + 8);
        Qlo[kc][0] = *(const uint32_t*)(Qlg + (size_t)rowA*HD + c0);
        Qlo[kc][1] = *(const uint32_t*)(Qlg + (size_t)rowB*HD + c0);
        Qlo[kc][2] = *(const uint32_t*)(Qlg + (size_t)rowA*HD + c0 + 8);
        Qlo[kc][3] = *(const uint32_t*)(Qlg + (size_t)rowB*HD + c0 + 8);
    }

    auto stage = [&](int kt, int bufi) {
        const int k0 = kt * 64;
        const uint32_t bb = sb + (uint32_t)bufi * AT_BUF;
        const int seg = tid & 7;
        const int r8  = tid >> 3;
        #pragma unroll
        for (int i = 0; i < 8; i++) {
            const int plane = i >> 1;
            const int row   = ((i & 1) << 5) + r8;
            const uint32_t dst = bb + (uint32_t)plane*AT_PL
                               + (uint32_t)(row*AT_PITCH + seg*16);
            const __nv_bfloat16* src =
                (plane == 0) ? Khg + (size_t)(k0 + row)*HD + seg*8 :
                (plane == 1) ? Klg + (size_t)(k0 + row)*HD + seg*8 :
                (plane == 2) ? Vhg + (size_t)row*SEQ + k0 + seg*8  :
                               Vlg + (size_t)row*SEQ + k0 + seg*8;
            cp16(dst, src);
        }
        asm volatile("cp.async.commit_group;" ::: "memory");
    };

    float o[8][4];
    #pragma unroll
    for (int dt = 0; dt < 8; dt++)
        #pragma unroll
        for (int i = 0; i < 4; i++) o[dt][i] = 0.f;
    float mA = -1e30f, mB = -1e30f, lA = 0.f, lB = 0.f;

    stage(0, 0);

    for (int kt = 0; kt < SEQ/64; kt++) {
        asm volatile("cp.async.wait_group 0;" ::: "memory");
        __syncthreads();
        if (kt + 1 < SEQ/64) stage(kt + 1, (kt + 1) & 1);

        const int k0 = kt * 64;
        const uint32_t bb = sb + (uint32_t)(kt & 1) * AT_BUF;

        // ---- QK: S[16][64] (log2 domain), ldmatrix + 3 planes ----
        float c[8][4];
        #pragma unroll
        for (int nt = 0; nt < 8; nt++)
            #pragma unroll
            for (int i = 0; i < 4; i++) c[nt][i] = 0.f;

        #pragma unroll
        for (int kc = 0; kc < 4; kc++) {
            #pragma unroll
            for (int p = 0; p < 4; p++) {
                const uint32_t ro = (uint32_t)(p*16*AT_PITCH + kc*32) + tB;
                uint32_t Bh[4], Bl[4];
                ldsm4(Bh, bb + ro);
                ldsm4(Bl, bb + AT_PL + ro);
                mma16816(c[2*p],   Qhi[kc], Bh);
                mma16816(c[2*p],   Qlo[kc], Bh);
                mma16816(c[2*p],   Qhi[kc], Bl);
                mma16816(c[2*p+1], Qhi[kc], Bh + 2);
                mma16816(c[2*p+1], Qlo[kc], Bh + 2);
                mma16816(c[2*p+1], Qhi[kc], Bl + 2);
            }
        }

        // ---- bias (arithmetic QWK, log2 domain) + mask ----
        #pragma unroll
        for (int nt = 0; nt < 8; nt++) {
            const int col = k0 + nt*8 + tg*2;
            float2 rk2 = *(const float2*)(rkf + col);
            int2 mvA = *(const int2*)(Mb + (size_t)rowA*SEQ + col);
            int2 mvB = *(const int2*)(Mb + (size_t)rowB*SEQ + col);
            float d0 = rqA - rk2.x, d1 = rqA - rk2.y;
            float d2 = rqB - rk2.x, d3 = rqB - rk2.y;
            c[nt][0] = (mvA.x == 0) ? -1e9f : c[nt][0] + A0c - A1c*d0*d0;
            c[nt][1] = (mvA.y == 0) ? -1e9f : c[nt][1] + A0c - A1c*d1*d1;
            c[nt][2] = (mvB.x == 0) ? -1e9f : c[nt][2] + A0c - A1c*d2*d2;
            c[nt][3] = (mvB.y == 0) ? -1e9f : c[nt][3] + A0c - A1c*d3*d3;
        }

        // ---- online softmax (base-2) ----
        float mxA = -1e30f, mxB = -1e30f;
        #pragma unroll
        for (int nt = 0; nt < 8; nt++) {
            mxA = fmaxf(mxA, fmaxf(c[nt][0], c[nt][1]));
            mxB = fmaxf(mxB, fmaxf(c[nt][2], c[nt][3]));
        }
        mxA = fmaxf(mxA, __shfl_xor_sync(0xffffffffu, mxA, 1));
        mxA = fmaxf(mxA, __shfl_xor_sync(0xffffffffu, mxA, 2));
        mxB = fmaxf(mxB, __shfl_xor_sync(0xffffffffu, mxB, 1));
        mxB = fmaxf(mxB, __shfl_xor_sync(0xffffffffu, mxB, 2));

        const float mnA = fmaxf(mA, mxA), mnB = fmaxf(mB, mxB);
        const float alA = ex2(mA - mnA), alB = ex2(mB - mnB);
        mA = mnA; mB = mnB;

        float rsA = 0.f, rsB = 0.f;
        #pragma unroll
        for (int nt = 0; nt < 8; nt++) {
            c[nt][0] = ex2(c[nt][0] - mnA);  rsA += c[nt][0];
            c[nt][1] = ex2(c[nt][1] - mnA);  rsA += c[nt][1];
            c[nt][2] = ex2(c[nt][2] - mnB);  rsB += c[nt][2];
            c[nt][3] = ex2(c[nt][3] - mnB);  rsB += c[nt][3];
        }
        rsA += __shfl_xor_sync(0xffffffffu, rsA, 1);
        rsA += __shfl_xor_sync(0xffffffffu, rsA, 2);
        rsB += __shfl_xor_sync(0xffffffffu, rsB, 1);
        rsB += __shfl_xor_sync(0xffffffffu, rsB, 2);
        lA = lA * alA + rsA;
        lB = lB * alB + rsB;

        #pragma unroll
        for (int dt = 0; dt < 8; dt++) {
            o[dt][0] *= alA; o[dt][1] *= alA;
            o[dt][2] *= alB; o[dt][3] *= alB;
        }

        // ---- P c-frags -> PV A-frags, bf16 hi/lo ----
        uint32_t Phi[4][4], Plo[4][4];
        #pragma unroll
        for (int kc = 0; kc < 4; kc++) {
            split2(c[2*kc  ][0], c[2*kc  ][1], Phi[kc][0], Plo[kc][0]);
            split2(c[2*kc  ][2], c[2*kc  ][3], Phi[kc][1], Plo[kc][1]);
            split2(c[2*kc+1][0], c[2*kc+1][1], Phi[kc][2], Plo[kc][2]);
            split2(c[2*kc+1][2], c[2*kc+1][3], Phi[kc][3], Plo[kc][3]);
        }

        // ---- PV: O += P @ V, ldmatrix + 3 planes ----
        #pragma unroll
        for (int kc = 0; kc < 4; kc++) {
            #pragma unroll
            for (int p = 0; p < 4; p++) {
                const uint32_t ro = (uint32_t)(p*16*AT_PITCH + kc*32) + tB;
                uint32_t Vh[4], Vl[4];
                ldsm4(Vh, bb + 2*AT_PL + ro);
                ldsm4(Vl, bb + 3*AT_PL + ro);
                mma16816(o[2*p],   Phi[kc], Vh);
                mma16816(o[2*p],   Plo[kc], Vh);
                mma16816(o[2*p],   Phi[kc], Vl);
                mma16816(o[2*p+1], Phi[kc], Vh + 2);
                mma16816(o[2*p+1], Plo[kc], Vh + 2);
                mma16816(o[2*p+1], Phi[kc], Vl + 2);
            }
        }
    }

    // ---- epilogue: normalize, store fp32 [B,H,S,D] ----
    const float invA = 1.0f / lA, invB = 1.0f / lB;
    float* Og = g_att + hb64;
    #pragma unroll
    for (int dt = 0; dt < 8; dt++) {
        const int col = dt*8 + tg*2;
        float2 vA, vB;
        vA.x = o[dt][0] * invA;  vA.y = o[dt][1] * invA;
        vB.x = o[dt][2] * invB;  vB.y = o[dt][3] * invB;
        *(float2*)(Og + (size_t)rowA*HD + col) = vA;
        *(float2*)(Og + (size_t)rowB*HD + col) = vB;
    }
}

// ===========================================================================
extern "C" void kernel_launch(void* const* d_in, const int* in_sizes, int n_in,
                              void* d_out, int out_size)
{
    const float* query     = (const float*)d_in[0];
    const float* key_      = (const float*)d_in[1];
    const float* value     = (const float*)d_in[2];
    const int*   responses = (const int*)  d_in[3];
    const int*   mask      = (const int*)  d_in[4];
    const float* Wq = (const float*)d_in[5];
    const float* bq = (const float*)d_in[6];
    const float* Wk = (const float*)d_in[7];
    const float* bk = (const float*)d_in[8];
    const float* Wv = (const float*)d_in[9];
    const float* bv = (const float*)d_in[10];
    const float* Wo = (const float*)d_in[11];
    const float* bo = (const float*)d_in[12];
    const float* Wm = (const float*)d_in[13];
    const float* bmv = (const float*)d_in[14];
    float* out = (float*)d_out;

    __nv_bfloat16 *qh, *ql, *kh, *kl, *vh, *vl;
    float* ap;
    cudaGetSymbolAddress((void**)&qh, g_Qhi);
    cudaGetSymbolAddress((void**)&ql, g_Qlo);
    cudaGetSymbolAddress((void**)&kh, g_Khi);
    cudaGetSymbolAddress((void**)&kl, g_Klo);
    cudaGetSymbolAddress((void**)&vh, g_Vhi);
    cudaGetSymbolAddress((void**)&vl, g_Vlo);
    cudaGetSymbolAddress((void**)&ap, g_att);

    cudaFuncSetAttribute(qkv_mma,   cudaFuncAttributeMaxDynamicSharedMemorySize, PJ_SMEM);
    cudaFuncSetAttribute(oproj_mma, cudaFuncAttributeMaxDynamicSharedMemorySize, PJ_SMEM);
    cudaFuncSetAttribute(attn_mma,  cudaFuncAttributeMaxDynamicSharedMemorySize, AT_SMEM);

    // Merged Q/K/V projections: one launch, 768 CTAs of 512 threads
    dim3 qgrid(EMB/128, (BATCH*SEQ)/128, 3);   // (8, 32, 3)
    qkv_mma<<<qgrid, PJ_THR, PJ_SMEM>>>(query, key_, value, Wq, Wk, Wv,
                                        bq, bk, bv, qh, ql, kh, kl, vh, vl);

    dim3 agrid(SEQ/128, NH, BATCH);            // (16, 16, 2)
    attn_mma<<<agrid, 256, AT_SMEM>>>(responses, mask, Wm, bmv);

    dim3 pgrid(EMB/128, (BATCH*SEQ)/128);      // (8, 32)
    oproj_mma<<<pgrid, PJ_THR, PJ_SMEM>>>(ap, Wo, bo, out);
}

// round 17
// speedup vs baseline: 1.1167x; 1.1167x over previous
#include <cuda_runtime.h>
#include <cuda_bf16.h>
#include <math.h>
#include <stdint.h>

#define BATCH 2
#define SEQ   2048
#define EMB   1024
#define NH    16
#define HD    64

#define ACT_N   (BATCH*SEQ*EMB)     // 4194304 elems per activation
#define W_N     (EMB*EMB)           // 1048576 elems per weight

// Pre-split bf16 planes.
// Attention operands: Q/K [B,H,S,D], V transposed [B,H,D,S]. Q scaled log2e/8.
__device__ __nv_bfloat16 g_Qhi[BATCH*NH*SEQ*HD];
__device__ __nv_bfloat16 g_Qlo[BATCH*NH*SEQ*HD];
__device__ __nv_bfloat16 g_Khi[BATCH*NH*SEQ*HD];
__device__ __nv_bfloat16 g_Klo[BATCH*NH*SEQ*HD];
__device__ __nv_bfloat16 g_Vhi[BATCH*NH*SEQ*HD];
__device__ __nv_bfloat16 g_Vlo[BATCH*NH*SEQ*HD];
// GEMM inputs pre-split by the prepass: activations (q,k,v) and weights (Wq,Wk,Wv,Wo)
__device__ __nv_bfloat16 g_Ahi[3*ACT_N];
__device__ __nv_bfloat16 g_Alo[3*ACT_N];
__device__ __nv_bfloat16 g_WhiP[4*W_N];
__device__ __nv_bfloat16 g_WloP[4*W_N];
// Attention output, written pre-split by attn epilogue, consumed by oproj
__device__ __nv_bfloat16 g_Ohi[BATCH*NH*SEQ*HD];
__device__ __nv_bfloat16 g_Olo[BATCH*NH*SEQ*HD];

#define LOG2E 1.4426950408889634f

// ===========================================================================
// helpers
// ===========================================================================
__device__ __forceinline__ uint32_t smem_u32(const void* p) {
    uint32_t a;
    asm("{ .reg .u64 t; cvta.to.shared.u64 t, %1; cvt.u32.u64 %0, t; }"
        : "=r"(a) : "l"(p));
    return a;
}
__device__ __forceinline__ void cp16(uint32_t dst, const void* src) {
    asm volatile("cp.async.cg.shared.global [%0], [%1], 16;"
                 :: "r"(dst), "l"(src) : "memory");
}
__device__ __forceinline__ float ex2(float x) {
    float r;
    asm("ex2.approx.f32 %0, %1;" : "=f"(r) : "f"(x));
    return r;
}
__device__ __forceinline__ void ldsm4(uint32_t* r, uint32_t addr) {
    asm volatile("ldmatrix.sync.aligned.m8n8.x4.shared.b16 {%0,%1,%2,%3}, [%4];"
                 : "=r"(r[0]), "=r"(r[1]), "=r"(r[2]), "=r"(r[3]) : "r"(addr));
}
__device__ __forceinline__ void mma16816(float* c, const uint32_t* a, const uint32_t* b) {
    asm volatile(
        "mma.sync.aligned.m16n8k16.row.col.f32.bf16.bf16.f32 "
        "{%0,%1,%2,%3}, {%4,%5,%6,%7}, {%8,%9}, {%0,%1,%2,%3};"
        : "+f"(c[0]), "+f"(c[1]), "+f"(c[2]), "+f"(c[3])
        : "r"(a[0]), "r"(a[1]), "r"(a[2]), "r"(a[3]), "r"(b[0]), "r"(b[1]));
}
__device__ __forceinline__ uint32_t pkbf(__nv_bfloat16 a, __nv_bfloat16 b) {
    return ((uint32_t)__bfloat16_as_ushort(b) << 16) | __bfloat16_as_ushort(a);
}
__device__ __forceinline__ void split2(float x, float y, uint32_t& hi, uint32_t& lo) {
    __nv_bfloat16 hx = __float2bfloat16(x);
    __nv_bfloat16 hy = __float2bfloat16(y);
    hi = pkbf(hx, hy);
    lo = pkbf(__float2bfloat16(x - __bfloat162float(hx)),
              __float2bfloat16(y - __bfloat162float(hy)));
}
__device__ __forceinline__ uint4 split4(float4 v) {
    uint4 u;
    split2(v.x, v.y, u.x, u.z);
    split2(v.z, v.w, u.y, u.w);
    return u;
}

// ===========================================================================
// Prepass: split fp32 tensors into bf16 hi/lo planes in global.
// z<3: activations (q,k,v), 4M elems each. z>=3: weights (Wq,Wk,Wv,Wo), 1M.
// ===========================================================================
__global__ void __launch_bounds__(256)
split_pre(const float* __restrict__ q, const float* __restrict__ k,
          const float* __restrict__ v,
          const float* __restrict__ Wq, const float* __restrict__ Wk,
          const float* __restrict__ Wv, const float* __restrict__ Wo,
          __nv_bfloat16* __restrict__ Ahi, __nv_bfloat16* __restrict__ Alo,
          __nv_bfloat16* __restrict__ Whi, __nv_bfloat16* __restrict__ Wlo)
{
    const int z = blockIdx.z;
    const float* src;
    __nv_bfloat16 *hi, *lo;
    int n4;
    if (z < 3) {
        src = (z == 0) ? q : (z == 1) ? k : v;
        hi = Ahi + (size_t)z * ACT_N;
        lo = Alo + (size_t)z * ACT_N;
        n4 = ACT_N / 4;
    } else {
        const int w = z - 3;
        src = (w == 0) ? Wq : (w == 1) ? Wk : (w == 2) ? Wv : Wo;
        hi = Whi + (size_t)w * W_N;
        lo = Wlo + (size_t)w * W_N;
        n4 = W_N / 4;
    }
    for (int i = blockIdx.x * blockDim.x + threadIdx.x; i < n4;
         i += gridDim.x * blockDim.x) {
        float4 v4 = ((const float4*)src)[i];
        uint4 u = split4(v4);
        ((uint2*)hi)[i] = make_uint2(u.x, u.y);
        ((uint2*)lo)[i] = make_uint2(u.z, u.w);
    }
}

// ===========================================================================
// Projection GEMM core: 4096x1024 @ 1024x1024^T, bf16 3-plane split.
// CTA 128x128, 256 threads / 8 warps (2Mx4N), warp tile 64x32, BK=32,
// cp.async double-buffered from PRE-SPLIT planes (no in-loop conversion),
// pitch 80B, fragments via ldmatrix.x4. 2 CTAs/SM target.
// ===========================================================================
#define BK      32
#define PITCHB  80
#define PLANE   (128*PITCHB)        // 10240
#define BUFSZ   (4*PLANE)           // 40960
#define PJ_SMEM (2*BUFSZ)           // 81920

__device__ __forceinline__ uint32_t asel(int lane) {
    return (uint32_t)(((lane & 7) + ((lane >> 3) & 1) * 8) * PITCHB + (lane >> 4) * 16);
}
__device__ __forceinline__ uint32_t bsel(int lane, int pitch) {
    return (uint32_t)((((lane >> 4) << 3) | (lane & 7)) * pitch + ((lane & 8) ? 16 : 0));
}

// MODEA: 0 = A planes linear [m][k], 1 = A planes from [B,H,S,D] (attn out).
template<int MODEA>
__device__ __forceinline__ void proj_body_cp(
    const __nv_bfloat16* __restrict__ Ahi, const __nv_bfloat16* __restrict__ Alo,
    const __nv_bfloat16* __restrict__ Whi, const __nv_bfloat16* __restrict__ Wlo,
    uint32_t sb, int m0, int n0, float acc[4][4][4])
{
    const int tid  = threadIdx.x;
    const int wid  = tid >> 5, lane = tid & 31;
    const int wM   = wid >> 2;          // 0..1
    const int wN   = wid & 3;           // 0..3
    const uint32_t tA = asel(lane);
    const uint32_t tB = bsel(lane, PITCHB);

    auto stage = [&](int kb, int bufi) {
        const int k0 = kb * BK;
        const uint32_t bb = sb + (uint32_t)bufi * BUFSZ;
        #pragma unroll
        for (int i = 0; i < 8; i++) {
            const int plane = i >> 1;                  // compile-time per i
            const int c   = ((i & 1) << 8) + tid;      // 0..511
            const int row = c >> 2, seg = c & 3;
            const uint32_t dst = bb + (uint32_t)(plane*PLANE + row*PITCHB + seg*16);
            const __nv_bfloat16* src;
            if (plane < 2) {
                const __nv_bfloat16* base = plane ? Alo : Ahi;
                if (MODEA == 1) {
                    const int m = m0 + row;
                    const int b = m >> 11, s = m & 2047;
                    const int kk = k0 + seg*8;
                    const int h = kk >> 6, d = kk & 63;
                    src = base + ((size_t)((b*NH + h)*SEQ + s))*HD + d;
                } else {
                    src = base + (size_t)(m0 + row)*EMB + k0 + seg*8;
                }
            } else {
                const __nv_bfloat16* base = (plane == 2) ? Whi : Wlo;
                src = base + (size_t)(n0 + row)*EMB + k0 + seg*8;
            }
            cp16(dst, src);
        }
        asm volatile("cp.async.commit_group;" ::: "memory");
    };

    auto mma_chunk = [&](int bufi) {
        const uint32_t aH = sb + (uint32_t)bufi * BUFSZ;
        #pragma unroll
        for (int ks = 0; ks < 2; ks++) {
            const uint32_t kOff = (uint32_t)(ks * 32);
            uint32_t Ah[4][4], Al[4][4], Bh[2][4], Bl[2][4];
            #pragma unroll
            for (int mt = 0; mt < 4; mt++) {
                const uint32_t ro = (uint32_t)((wM*64 + mt*16) * PITCHB) + kOff + tA;
                ldsm4(Ah[mt], aH + ro);
                ldsm4(Al[mt], aH + PLANE + ro);
            }
            #pragma unroll
            for (int p = 0; p < 2; p++) {
                const uint32_t ro = (uint32_t)((wN*32 + p*16) * PITCHB) + kOff + tB;
                ldsm4(Bh[p], aH + 2*PLANE + ro);
                ldsm4(Bl[p], aH + 3*PLANE + ro);
            }
            #pragma unroll
            for (int mt = 0; mt < 4; mt++)
                #pragma unroll
                for (int p = 0; p < 2; p++) {
                    mma16816(acc[mt][2*p],   Ah[mt], Bh[p]);
                    mma16816(acc[mt][2*p],   Al[mt], Bh[p]);
                    mma16816(acc[mt][2*p],   Ah[mt], Bl[p]);
                    mma16816(acc[mt][2*p+1], Ah[mt], Bh[p] + 2);
                    mma16816(acc[mt][2*p+1], Al[mt], Bh[p] + 2);
                    mma16816(acc[mt][2*p+1], Ah[mt], Bl[p] + 2);
                }
        }
    };

    stage(0, 0);
    for (int kb = 0; kb < EMB/BK; kb++) {
        asm volatile("cp.async.wait_group 0;" ::: "memory");
        __syncthreads();
        if (kb < EMB/BK - 1) stage(kb + 1, (kb + 1) & 1);
        mma_chunk(kb & 1);
    }
}

// Merged Q/K/V projection: blockIdx.z selects {query,key,value}.
// z<2 -> bf16 planes [B,H,S,D]; z==2 -> planes transposed [B,H,D,S].
__global__ void __launch_bounds__(256, 2)
qkv_mma(const float* __restrict__ bq, const float* __restrict__ bk,
        const float* __restrict__ bv,
        __nv_bfloat16* __restrict__ qh, __nv_bfloat16* __restrict__ ql,
        __nv_bfloat16* __restrict__ kh, __nv_bfloat16* __restrict__ kl,
        __nv_bfloat16* __restrict__ vh, __nv_bfloat16* __restrict__ vl)
{
    extern __shared__ char smp[];
    const uint32_t sb = smem_u32(smp);
    const int z = blockIdx.z;
    const __nv_bfloat16* ah = g_Ahi  + (size_t)z * ACT_N;
    const __nv_bfloat16* al = g_Alo  + (size_t)z * ACT_N;
    const __nv_bfloat16* wh = g_WhiP + (size_t)z * W_N;
    const __nv_bfloat16* wl = g_WloP + (size_t)z * W_N;
    const float* bias = (z == 0) ? bq : (z == 1) ? bk : bv;
    __nv_bfloat16* Chi = (z == 0) ? qh : (z == 1) ? kh : vh;
    __nv_bfloat16* Clo = (z == 0) ? ql : (z == 1) ? kl : vl;
    const float scale = (z == 0) ? 0.125f * LOG2E : 1.0f;

    const int n0 = blockIdx.x * 128;
    const int m0 = blockIdx.y * 128;

    float acc[4][4][4];
    #pragma unroll
    for (int mt = 0; mt < 4; mt++)
        #pragma unroll
        for (int nt = 0; nt < 4; nt++)
            #pragma unroll
            for (int i = 0; i < 4; i++) acc[mt][nt][i] = 0.f;

    proj_body_cp<0>(ah, al, wh, wl, sb, m0, n0, acc);

    const int tid = threadIdx.x;
    const int wid = tid >> 5, lane = tid & 31;
    const int g = lane >> 2, tg = lane & 3;
    const int wM = wid >> 2, wN = wid & 3;

    #pragma unroll
    for (int mt = 0; mt < 4; mt++) {
        #pragma unroll
        for (int nt = 0; nt < 4; nt++) {
            const int row0 = m0 + wM*64 + mt*16 + g;
            const int col  = n0 + wN*32 + nt*8 + tg*2;
            float2 bv2 = *(const float2*)(bias + col);
            float2 v0, v1;
            v0.x = (acc[mt][nt][0] + bv2.x) * scale;
            v0.y = (acc[mt][nt][1] + bv2.y) * scale;
            v1.x = (acc[mt][nt][2] + bv2.x) * scale;
            v1.y = (acc[mt][nt][3] + bv2.y) * scale;
            const int h = col >> 6, d = col & 63;
            if (z < 2) {
                uint32_t hi, lo;
                {
                    const int b = row0 >> 11, s = row0 & 2047;
                    const size_t idx = ((size_t)((b*NH + h)*SEQ + s))*HD + d;
                    split2(v0.x, v0.y, hi, lo);
                    *(uint32_t*)(Chi + idx) = hi;
                    *(uint32_t*)(Clo + idx) = lo;
                }
                {
                    const int r1 = row0 + 8;
                    const int b = r1 >> 11, s = r1 & 2047;
                    const size_t idx = ((size_t)((b*NH + h)*SEQ + s))*HD + d;
                    split2(v1.x, v1.y, hi, lo);
                    *(uint32_t*)(Chi + idx) = hi;
                    *(uint32_t*)(Clo + idx) = lo;
                }
            } else {
                const int b = row0 >> 11, s = row0 & 2047;
                __nv_bfloat16* bhp = Chi + ((size_t)(b*NH + h))*HD*SEQ;
                __nv_bfloat16* blp = Clo + ((size_t)(b*NH + h))*HD*SEQ;
                #pragma unroll
                for (int qq = 0; qq < 4; qq++) {
                    const float vv = (qq==0) ? v0.x : (qq==1) ? v0.y : (qq==2) ? v1.x : v1.y;
                    const int dd = d + (qq & 1);
                    const int ss = s + ((qq >> 1) << 3);
                    __nv_bfloat16 hb = __float2bfloat16(vv);
                    __nv_bfloat16 lb = __float2bfloat16(vv - __bfloat162float(hb));
                    bhp[(size_t)dd*SEQ + ss] = hb;
                    blp[(size_t)dd*SEQ + ss] = lb;
                }
            }
        }
    }
}

// Output projection: A planes from attn output [B,H,S,D], C fp32 linear.
__global__ void __launch_bounds__(256, 2)
oproj_mma(const float* __restrict__ bias, float* __restrict__ Cf)
{
    extern __shared__ char smp[];
    const uint32_t sb = smem_u32(smp);
    const int n0 = blockIdx.x * 128;
    const int m0 = blockIdx.y * 128;

    float acc[4][4][4];
    #pragma unroll
    for (int mt = 0; mt < 4; mt++)
        #pragma unroll
        for (int nt = 0; nt < 4; nt++)
            #pragma unroll
            for (int i = 0; i < 4; i++) acc[mt][nt][i] = 0.f;

    proj_body_cp<1>(g_Ohi, g_Olo, g_WhiP + 3*(size_t)W_N, g_WloP + 3*(size_t)W_N,
                    sb, m0, n0, acc);

    const int tid = threadIdx.x;
    const int wid = tid >> 5, lane = tid & 31;
    const int g = lane >> 2, tg = lane & 3;
    const int wM = wid >> 2, wN = wid & 3;

    #pragma unroll
    for (int mt = 0; mt < 4; mt++) {
        #pragma unroll
        for (int nt = 0; nt < 4; nt++) {
            const int row0 = m0 + wM*64 + mt*16 + g;
            const int col  = n0 + wN*32 + nt*8 + tg*2;
            float2 bv = *(const float2*)(bias + col);
            float2 v0, v1;
            v0.x = acc[mt][nt][0] + bv.x;  v0.y = acc[mt][nt][1] + bv.y;
            v1.x = acc[mt][nt][2] + bv.x;  v1.y = acc[mt][nt][3] + bv.y;
            *(float2*)(Cf + (size_t)row0 * EMB + col) = v0;
            *(float2*)(Cf + (size_t)(row0 + 8) * EMB + col) = v1;
        }
    }
}

// ===========================================================================
// Flash attention via warp-level bf16 MMA. CTA: 8 warps x 16 q-rows = 128.
// K/V tiles staged by cp.async from pre-split planes, double-buffered.
// ldmatrix.x4 fragments. Softmax base-2. 2 CTAs/SM (128 regs).
// Epilogue writes PRE-SPLIT output planes for the O projection.
// ===========================================================================
#define AT_PITCH 144
#define AT_PL    (64*AT_PITCH)          // 9216 per plane
#define AT_BUF   (4*AT_PL)              // 36864
#define AT_RK    (2*AT_BUF)             // 73728
#define AT_SMEM  (AT_RK + SEQ*4)        // 81920

__global__ void __launch_bounds__(256, 2)
attn_mma(const int* __restrict__ responses, const int* __restrict__ mask,
         const float* __restrict__ Wm, const float* __restrict__ bm)
{
    extern __shared__ char sma[];
    const uint32_t sb = smem_u32(sma);
    float* rkf = (float*)(sma + AT_RK);

    const int tid  = threadIdx.x;
    const int wid  = tid >> 5, lane = tid & 31;
    const int g    = lane >> 2, tg = lane & 3;
    const int qb = blockIdx.x, h = blockIdx.y, b = blockIdx.z;
    const int q0 = qb * 128;
    const int rowA = q0 + wid * 16 + g;
    const int rowB = rowA + 8;
    const uint32_t tB = bsel(lane, AT_PITCH);

    const float Wmh = Wm[h], bmh = bm[h];
    const float A0c = (Wmh + bmh) * LOG2E;
    const float A1c = Wmh * 0.0625f * LOG2E;
    const float rqA = (float)responses[b*SEQ + rowA];
    const float rqB = (float)responses[b*SEQ + rowB];

    const size_t hb64 = (size_t)(b*NH + h) * SEQ * HD;
    const __nv_bfloat16* Qhg = g_Qhi + hb64;
    const __nv_bfloat16* Qlg = g_Qlo + hb64;
    const __nv_bfloat16* Khg = g_Khi + hb64;
    const __nv_bfloat16* Klg = g_Klo + hb64;
    const __nv_bfloat16* Vhg = g_Vhi + hb64;   // [d][s]
    const __nv_bfloat16* Vlg = g_Vlo + hb64;
    const int*   Mb  = mask + (size_t)b*SEQ*SEQ;
    const int*   rkp = responses + b*SEQ;

    for (int i = tid; i < SEQ; i += 256) rkf[i] = (float)rkp[i];

    uint32_t Qhi[4][4], Qlo[4][4];
    #pragma unroll
    for (int kc = 0; kc < 4; kc++) {
        const int c0 = kc*16 + tg*2;
        Qhi[kc][0] = *(const uint32_t*)(Qhg + (size_t)rowA*HD + c0);
        Qhi[kc][1] = *(const uint32_t*)(Qhg + (size_t)rowB*HD + c0);
        Qhi[kc][2] = *(const uint32_t*)(Qhg + (size_t)rowA*HD + c0 + 8);
        Qhi[kc][3] = *(const uint32_t*)(Qhg + (size_t)rowB*HD + c0 + 8);
        Qlo[kc][0] = *(const uint32_t*)(Qlg + (size_t)rowA*HD + c0);
        Qlo[kc][1] = *(const uint32_t*)(Qlg + (size_t)rowB*HD + c0);
        Qlo[kc][2] = *(const uint32_t*)(Qlg + (size_t)rowA*HD + c0 + 8);
        Qlo[kc][3] = *(const uint32_t*)(Qlg + (size_t)rowB*HD + c0 + 8);
    }

    auto stage = [&](int kt, int bufi) {
        const int k0 = kt * 64;
        const uint32_t bb = sb + (uint32_t)bufi * AT_BUF;
        const int seg = tid & 7;
        const int r8  = tid >> 3;
        #pragma unroll
        for (int i = 0; i < 8; i++) {
            const int plane = i >> 1;
            const int row   = ((i & 1) << 5) + r8;
            const uint32_t dst = bb + (uint32_t)plane*AT_PL
                               + (uint32_t)(row*AT_PITCH + seg*16);
            const __nv_bfloat16* src =
                (plane == 0) ? Khg + (size_t)(k0 + row)*HD + seg*8 :
                (plane == 1) ? Klg + (size_t)(k0 + row)*HD + seg*8 :
                (plane == 2) ? Vhg + (size_t)row*SEQ + k0 + seg*8  :
                               Vlg + (size_t)row*SEQ + k0 + seg*8;
            cp16(dst, src);
        }
        asm volatile("cp.async.commit_group;" ::: "memory");
    };

    float o[8][4];
    #pragma unroll
    for (int dt = 0; dt < 8; dt++)
        #pragma unroll
        for (int i = 0; i < 4; i++) o[dt][i] = 0.f;
    float mA = -1e30f, mB = -1e30f, lA = 0.f, lB = 0.f;

    stage(0, 0);

    for (int kt = 0; kt < SEQ/64; kt++) {
        asm volatile("cp.async.wait_group 0;" ::: "memory");
        __syncthreads();
        if (kt + 1 < SEQ/64) stage(kt + 1, (kt + 1) & 1);

        const int k0 = kt * 64;
        const uint32_t bb = sb + (uint32_t)(kt & 1) * AT_BUF;

        float c[8][4];
        #pragma unroll
        for (int nt = 0; nt < 8; nt++)
            #pragma unroll
            for (int i = 0; i < 4; i++) c[nt][i] = 0.f;

        #pragma unroll
        for (int kc = 0; kc < 4; kc++) {
            #pragma unroll
            for (int p = 0; p < 4; p++) {
                const uint32_t ro = (uint32_t)(p*16*AT_PITCH + kc*32) + tB;
                uint32_t Bh[4], Bl[4];
                ldsm4(Bh, bb + ro);
                ldsm4(Bl, bb + AT_PL + ro);
                mma16816(c[2*p],   Qhi[kc], Bh);
                mma16816(c[2*p],   Qlo[kc], Bh);
                mma16816(c[2*p],   Qhi[kc], Bl);
                mma16816(c[2*p+1], Qhi[kc], Bh + 2);
                mma16816(c[2*p+1], Qlo[kc], Bh + 2);
                mma16816(c[2*p+1], Qhi[kc], Bl + 2);
            }
        }

        #pragma unroll
        for (int nt = 0; nt < 8; nt++) {
            const int col = k0 + nt*8 + tg*2;
            float2 rk2 = *(const float2*)(rkf + col);
            int2 mvA = *(const int2*)(Mb + (size_t)rowA*SEQ + col);
            int2 mvB = *(const int2*)(Mb + (size_t)rowB*SEQ + col);
            float d0 = rqA - rk2.x, d1 = rqA - rk2.y;
            float d2 = rqB - rk2.x, d3 = rqB - rk2.y;
            c[nt][0] = (mvA.x == 0) ? -1e9f : c[nt][0] + A0c - A1c*d0*d0;
            c[nt][1] = (mvA.y == 0) ? -1e9f : c[nt][1] + A0c - A1c*d1*d1;
            c[nt][2] = (mvB.x == 0) ? -1e9f : c[nt][2] + A0c - A1c*d2*d2;
            c[nt][3] = (mvB.y == 0) ? -1e9f : c[nt][3] + A0c - A1c*d3*d3;
        }

        float mxA = -1e30f, mxB = -1e30f;
        #pragma unroll
        for (int nt = 0; nt < 8; nt++) {
            mxA = fmaxf(mxA, fmaxf(c[nt][0], c[nt][1]));
            mxB = fmaxf(mxB, fmaxf(c[nt][2], c[nt][3]));
        }
        mxA = fmaxf(mxA, __shfl_xor_sync(0xffffffffu, mxA, 1));
        mxA = fmaxf(mxA, __shfl_xor_sync(0xffffffffu, mxA, 2));
        mxB = fmaxf(mxB, __shfl_xor_sync(0xffffffffu, mxB, 1));
        mxB = fmaxf(mxB, __shfl_xor_sync(0xffffffffu, mxB, 2));

        const float mnA = fmaxf(mA, mxA), mnB = fmaxf(mB, mxB);
        const float alA = ex2(mA - mnA), alB = ex2(mB - mnB);
        mA = mnA; mB = mnB;

        float rsA = 0.f, rsB = 0.f;
        #pragma unroll
        for (int nt = 0; nt < 8; nt++) {
            c[nt][0] = ex2(c[nt][0] - mnA);  rsA += c[nt][0];
            c[nt][1] = ex2(c[nt][1] - mnA);  rsA += c[nt][1];
            c[nt][2] = ex2(c[nt][2] - mnB);  rsB += c[nt][2];
            c[nt][3] = ex2(c[nt][3] - mnB);  rsB += c[nt][3];
        }
        rsA += __shfl_xor_sync(0xffffffffu, rsA, 1);
        rsA += __shfl_xor_sync(0xffffffffu, rsA, 2);
        rsB += __shfl_xor_sync(0xffffffffu, rsB, 1);
        rsB += __shfl_xor_sync(0xffffffffu, rsB, 2);
        lA = lA * alA + rsA;
        lB = lB * alB + rsB;

        #pragma unroll
        for (int dt = 0; dt < 8; dt++) {
            o[dt][0] *= alA; o[dt][1] *= alA;
            o[dt][2] *= alB; o[dt][3] *= alB;
        }

        uint32_t Phi[4][4], Plo[4][4];
        #pragma unroll
        for (int kc = 0; kc < 4; kc++) {
            split2(c[2*kc  ][0], c[2*kc  ][1], Phi[kc][0], Plo[kc][0]);
            split2(c[2*kc  ][2], c[2*kc  ][3], Phi[kc][1], Plo[kc][1]);
            split2(c[2*kc+1][0], c[2*kc+1][1], Phi[kc][2], Plo[kc][2]);
            split2(c[2*kc+1][2], c[2*kc+1][3], Phi[kc][3], Plo[kc][3]);
        }

        #pragma unroll
        for (int kc = 0; kc < 4; kc++) {
            #pragma unroll
            for (int p = 0; p < 4; p++) {
                const uint32_t ro = (uint32_t)(p*16*AT_PITCH + kc*32) + tB;
                uint32_t Vh[4], Vl[4];
                ldsm4(Vh, bb + 2*AT_PL + ro);
                ldsm4(Vl, bb + 3*AT_PL + ro);
                mma16816(o[2*p],   Phi[kc], Vh);
                mma16816(o[2*p],   Plo[kc], Vh);
                mma16816(o[2*p],   Phi[kc], Vl);
                mma16816(o[2*p+1], Phi[kc], Vh + 2);
                mma16816(o[2*p+1], Plo[kc], Vh + 2);
                mma16816(o[2*p+1], Phi[kc], Vl + 2);
            }
        }
    }

    // ---- epilogue: normalize, split, store bf16 planes [B,H,S,D] ----
    const float invA = 1.0f / lA, invB = 1.0f / lB;
    __nv_bfloat16* Ohg = g_Ohi + hb64;
    __nv_bfloat16* Olg = g_Olo + hb64;
    #pragma unroll
    for (int dt = 0; dt < 8; dt++) {
        const int col = dt*8 + tg*2;
        uint32_t hi, lo;
        split2(o[dt][0] * invA, o[dt][1] * invA, hi, lo);
        *(uint32_t*)(Ohg + (size_t)rowA*HD + col) = hi;
        *(uint32_t*)(Olg + (size_t)rowA*HD + col) = lo;
        split2(o[dt][2] * invB, o[dt][3] * invB, hi, lo);
        *(uint32_t*)(Ohg + (size_t)rowB*HD + col) = hi;
        *(uint32_t*)(Olg + (size_t)rowB*HD + col) = lo;
    }
}

// ===========================================================================
extern "C" void kernel_launch(void* const* d_in, const int* in_sizes, int n_in,
                              void* d_out, int out_size)
{
    const float* query     = (const float*)d_in[0];
    const float* key_      = (const float*)d_in[1];
    const float* value     = (const float*)d_in[2];
    const int*   responses = (const int*)  d_in[3];
    const int*   mask      = (const int*)  d_in[4];
    const float* Wq = (const float*)d_in[5];
    const float* bq = (const float*)d_in[6];
    const float* Wk = (const float*)d_in[7];
    const float* bk = (const float*)d_in[8];
    const float* Wv = (const float*)d_in[9];
    const float* bv = (const float*)d_in[10];
    const float* Wo = (const float*)d_in[11];
    const float* bo = (const float*)d_in[12];
    const float* Wm = (const float*)d_in[13];
    const float* bmv = (const float*)d_in[14];
    float* out = (float*)d_out;

    __nv_bfloat16 *qh, *ql, *kh, *kl, *vh, *vl, *ahi, *alo, *whi, *wlo;
    cudaGetSymbolAddress((void**)&qh,  g_Qhi);
    cudaGetSymbolAddress((void**)&ql,  g_Qlo);
    cudaGetSymbolAddress((void**)&kh,  g_Khi);
    cudaGetSymbolAddress((void**)&kl,  g_Klo);
    cudaGetSymbolAddress((void**)&vh,  g_Vhi);
    cudaGetSymbolAddress((void**)&vl,  g_Vlo);
    cudaGetSymbolAddress((void**)&ahi, g_Ahi);
    cudaGetSymbolAddress((void**)&alo, g_Alo);
    cudaGetSymbolAddress((void**)&whi, g_WhiP);
    cudaGetSymbolAddress((void**)&wlo, g_WloP);

    cudaFuncSetAttribute(qkv_mma,   cudaFuncAttributeMaxDynamicSharedMemorySize, PJ_SMEM);
    cudaFuncSetAttribute(oproj_mma, cudaFuncAttributeMaxDynamicSharedMemorySize, PJ_SMEM);
    cudaFuncSetAttribute(attn_mma,  cudaFuncAttributeMaxDynamicSharedMemorySize, AT_SMEM);

    // Prepass: split all GEMM inputs into bf16 hi/lo planes
    dim3 sgrid(1024, 1, 7);
    split_pre<<<sgrid, 256>>>(query, key_, value, Wq, Wk, Wv, Wo,
                              ahi, alo, whi, wlo);

    // Merged Q/K/V projections (cp.async from pre-split planes)
    dim3 qgrid(EMB/128, (BATCH*SEQ)/128, 3);   // (8, 32, 3)
    qkv_mma<<<qgrid, 256, PJ_SMEM>>>(bq, bk, bv, qh, ql, kh, kl, vh, vl);

    dim3 agrid(SEQ/128, NH, BATCH);            // (16, 16, 2)
    attn_mma<<<agrid, 256, AT_SMEM>>>(responses, mask, Wm, bmv);

    dim3 pgrid(EMB/128, (BATCH*SEQ)/128);      // (8, 32)
    oproj_mma<<<pgrid, 256, PJ_SMEM>>>(bo, out);
}